// round 13
// baseline (speedup 1.0000x reference)
#include <cuda_runtime.h>
#include <cuda_bf16.h>
#include <cuda_fp16.h>
#include <cstdint>

#define N_USERS   100000
#define N_NODES   150000
#define EMB_DIM   64
#define LPN       8             // lanes per node (each lane: 8 halves = 16 B)
#define MAXE      2000000
#define SCAN_CHUNK 1024
#define SCAN_BLOCKS ((N_NODES + SCAN_CHUNK - 1) / SCAN_CHUNK)  // 147

// ------------- static scratch (no allocations allowed) -----------------------
// g_hist is zero-initialized at module load; every launch leaves it re-zeroed.
__device__ int                g_is64;
__device__ int                g_hist[N_NODES];
__device__ int                g_off[N_NODES + 1];   // exclusive scan of degrees
__device__ unsigned long long g_agg[SCAN_BLOCKS];   // bit63=ready | aggregate
__device__ unsigned short     g_rank[MAXE];         // edge rank within its column
__device__ int                g_src[MAXE];          // CSR: source only
// half-precision z buffers (z = deg^{-1/2} * x): 64 halves (128 B) per node row
__device__ __half g_z0[(size_t)N_NODES * EMB_DIM];
__device__ __half g_z1[(size_t)N_NODES * EMB_DIM];
__device__ __half g_z2[(size_t)N_NODES * EMB_DIM];

// ------------- helpers --------------------------------------------------------
__device__ __forceinline__ void add8(float* acc, uint4 v) {
    float2 f0 = __half22float2(*(__half2*)&v.x);
    float2 f1 = __half22float2(*(__half2*)&v.y);
    float2 f2 = __half22float2(*(__half2*)&v.z);
    float2 f3 = __half22float2(*(__half2*)&v.w);
    acc[0] += f0.x; acc[1] += f0.y;
    acc[2] += f1.x; acc[3] += f1.y;
    acc[4] += f2.x; acc[5] += f2.y;
    acc[6] += f3.x; acc[7] += f3.y;
}

__device__ __forceinline__ int clampn(long long v) {
    if (v < 0) v = 0;
    if (v >= N_NODES) v = N_NODES - 1;
    return (int)v;
}

// ------------- tiny pre-pass: zero lookback flags + dtype detect -------------
__global__ void k_pre(const long long* __restrict__ ei) {
    int t = threadIdx.x;
    if (t < SCAN_BLOCKS) g_agg[t] = 0ULL;
    if (t == 0) {
        int ok = 1;
        for (int k = 0; k < 256; k++) {
            long long v = ei[k];
            if (v < 0 || v >= N_NODES) { ok = 0; break; }
        }
        g_is64 = ok;
    }
}

// degree histogram of col — the atomic's return value is the edge's rank
// within its column: store it (free CSR placement info).
__global__ void k_hist(const void* __restrict__ ei, int E) {
    int t = blockIdx.x * blockDim.x + threadIdx.x;
    int e = t * 2;
    if (e >= E) return;
    int c0, c1 = -1;
    if (g_is64) {
        longlong2 cc = __ldg(&((const longlong2*)ei)[(E + e) >> 1]);
        c0 = clampn(cc.x);
        if (e + 1 < E) c1 = clampn(cc.y);
    } else {
        int2 cc = __ldg(&((const int2*)ei)[(E + e) >> 1]);
        c0 = clampn((long long)cc.x);
        if (e + 1 < E) c1 = clampn((long long)cc.y);
    }
    g_rank[e] = (unsigned short)atomicAdd(&g_hist[c0], 1);
    if (c1 >= 0) g_rank[e + 1] = (unsigned short)atomicAdd(&g_hist[c1], 1);
}

// ------------- fused scan (decoupled lookback, single wave) + z0 init --------
// 147 blocks x 1024 threads: all blocks co-resident on 148 SMs, spin is safe.
// Also re-zeroes g_hist for the next launch (sole consumer of the histogram).
__global__ void __launch_bounds__(SCAN_CHUNK)
k_scan_init(const float4* __restrict__ emb) {
    __shared__ int   s[SCAN_CHUNK];
    __shared__ float sdis[SCAN_CHUNK];
    __shared__ int   sbase;

    int t   = threadIdx.x;
    int b   = blockIdx.x;
    int idx = b * SCAN_CHUNK + t;

    int val = (idx < N_NODES) ? g_hist[idx] : 0;
    if (idx < N_NODES) g_hist[idx] = 0;              // ready for next launch
    sdis[t] = (val > 0) ? rsqrtf((float)val) : 0.0f;
    s[t] = val;
    if (t == 0) sbase = 0;
    __syncthreads();

    // inclusive Hillis-Steele scan of the chunk
    for (int o = 1; o < SCAN_CHUNK; o <<= 1) {
        int v = (t >= o) ? s[t - o] : 0;
        __syncthreads();
        s[t] += v;
        __syncthreads();
    }
    int incl  = s[t];
    int total = s[SCAN_CHUNK - 1];

    // publish this block's aggregate (bit63 = ready flag, single-word protocol)
    if (t == 0)
        atomicExch(&g_agg[b], (1ULL << 63) | (unsigned long long)(unsigned)total);

    // lookback: thread t (< b) waits for predecessor t's aggregate
    if (t < b) {
        unsigned long long w;
        do { w = atomicAdd(&g_agg[t], 0ULL); } while (!(w >> 63));
        atomicAdd(&sbase, (int)(unsigned)w);
    }
    __syncthreads();
    int base = sbase;

    if (idx < N_NODES)      g_off[idx] = base + incl - val;   // exclusive start
    if (idx == N_NODES - 1) g_off[N_NODES] = base + incl;

    // ---- fused z0 init for this block's node chunk (coalesced) ----
    int vbase = b * SCAN_CHUNK * 16;
    #pragma unroll
    for (int k = 0; k < 16; k++) {
        int local = k * SCAN_CHUNK + t;          // 0 .. 16383
        int vi = vbase + local;
        if (vi >= N_NODES * 16) break;
        float dis = sdis[local >> 4];
        float4 v = __ldg(&emb[vi]);
        __half2 h0 = __floats2half2_rn(v.x * dis, v.y * dis);
        __half2 h1 = __floats2half2_rn(v.z * dis, v.w * dis);
        uint2 packed;
        packed.x = *(unsigned int*)&h0;
        packed.y = *(unsigned int*)&h1;
        ((uint2*)g_z0)[vi] = packed;
    }
}

// --- place edges: ZERO atomics — position = off[col] + rank (from k_hist) ----
__global__ void k_place(const void* __restrict__ ei, int E) {
    int t = blockIdx.x * blockDim.x + threadIdx.x;
    int e = t * 2;
    if (e >= E) return;
    int r0, c0, r1 = -1, c1 = -1;
    if (g_is64) {
        longlong2 rr = __ldg(&((const longlong2*)ei)[e >> 1]);
        longlong2 cc = __ldg(&((const longlong2*)ei)[(E + e) >> 1]);
        r0 = clampn(rr.x); c0 = clampn(cc.x);
        if (e + 1 < E) { r1 = clampn(rr.y); c1 = clampn(cc.y); }
    } else {
        int2 rr = __ldg(&((const int2*)ei)[e >> 1]);
        int2 cc = __ldg(&((const int2*)ei)[(E + e) >> 1]);
        r0 = clampn((long long)rr.x); c0 = clampn((long long)cc.x);
        if (e + 1 < E) { r1 = clampn((long long)rr.y); c1 = clampn((long long)cc.y); }
    }
    int p0 = __ldg(&g_off[c0]) + (int)g_rank[e];
    g_src[p0] = r0;
    if (r1 >= 0) {
        int p1 = __ldg(&g_off[c1]) + (int)g_rank[e + 1];
        g_src[p1] = r1;
    }
}

// ------------- gather layer: z_out[c] = (sum z_in[src]) / deg[c] -------------
__global__ void __launch_bounds__(256)
k_gather(const __half* __restrict__ zin, __half* __restrict__ zout) {
    int gid  = blockIdx.x * blockDim.x + threadIdx.x;
    int node = gid >> 3;
    int lane = gid & 7;
    if (node >= N_NODES) return;

    const uint4* __restrict__ x = (const uint4*)zin;
    int s = __ldg(&g_off[node]);
    int e = __ldg(&g_off[node + 1]);

    float acc[8] = {0.f, 0.f, 0.f, 0.f, 0.f, 0.f, 0.f, 0.f};
    int p = s;
    for (; p + 4 <= e; p += 4) {
        int s0 = __ldg(&g_src[p]);
        int s1 = __ldg(&g_src[p + 1]);
        int s2 = __ldg(&g_src[p + 2]);
        int s3 = __ldg(&g_src[p + 3]);
        uint4 v0 = __ldg(&x[s0 * LPN + lane]);
        uint4 v1 = __ldg(&x[s1 * LPN + lane]);
        uint4 v2 = __ldg(&x[s2 * LPN + lane]);
        uint4 v3 = __ldg(&x[s3 * LPN + lane]);
        add8(acc, v0);
        add8(acc, v1);
        add8(acc, v2);
        add8(acc, v3);
    }
    for (; p < e; p++) {
        uint4 v0 = __ldg(&x[__ldg(&g_src[p]) * LPN + lane]);
        add8(acc, v0);
    }

    int deg = e - s;
    float inv = (deg > 0) ? (1.0f / (float)deg) : 0.0f;
    __half2 o0 = __floats2half2_rn(acc[0] * inv, acc[1] * inv);
    __half2 o1 = __floats2half2_rn(acc[2] * inv, acc[3] * inv);
    __half2 o2 = __floats2half2_rn(acc[4] * inv, acc[5] * inv);
    __half2 o3 = __floats2half2_rn(acc[6] * inv, acc[7] * inv);
    uint4 packed;
    packed.x = *(unsigned int*)&o0;
    packed.y = *(unsigned int*)&o1;
    packed.z = *(unsigned int*)&o2;
    packed.w = *(unsigned int*)&o3;
    ((uint4*)zout)[node * LPN + lane] = packed;
}

// ------------- final gather fused with combine -------------------------------
// S3 = sum z2[src]; out = (emb + (z1+z2)*sqrt(deg) + S3*rsqrt(deg)) / 4
__global__ void __launch_bounds__(256)
k_gather_final(const __half* __restrict__ z2h,
               const __half* __restrict__ z1h,
               const float4* __restrict__ emb,
               float4* __restrict__ out) {
    int gid  = blockIdx.x * blockDim.x + threadIdx.x;
    int node = gid >> 3;
    int lane = gid & 7;
    if (node >= N_NODES) return;

    const uint4* __restrict__ x = (const uint4*)z2h;
    int s = __ldg(&g_off[node]);
    int e = __ldg(&g_off[node + 1]);

    float acc[8] = {0.f, 0.f, 0.f, 0.f, 0.f, 0.f, 0.f, 0.f};
    int p = s;
    for (; p + 4 <= e; p += 4) {
        int s0 = __ldg(&g_src[p]);
        int s1 = __ldg(&g_src[p + 1]);
        int s2 = __ldg(&g_src[p + 2]);
        int s3 = __ldg(&g_src[p + 3]);
        uint4 v0 = __ldg(&x[s0 * LPN + lane]);
        uint4 v1 = __ldg(&x[s1 * LPN + lane]);
        uint4 v2 = __ldg(&x[s2 * LPN + lane]);
        uint4 v3 = __ldg(&x[s3 * LPN + lane]);
        add8(acc, v0);
        add8(acc, v1);
        add8(acc, v2);
        add8(acc, v3);
    }
    for (; p < e; p++) {
        uint4 v0 = __ldg(&x[__ldg(&g_src[p]) * LPN + lane]);
        add8(acc, v0);
    }

    int deg = e - s;
    float fdeg = (float)deg;
    float rsq  = (deg > 0) ? rsqrtf(fdeg) : 0.0f;   // x3 scale
    float sq   = (deg > 0) ? sqrtf(fdeg)  : 0.0f;   // x1,x2 scale

    uint4 a1 = ((const uint4*)z1h)[node * LPN + lane];
    uint4 a2 = x[node * LPN + lane];
    float zs[8] = {0.f, 0.f, 0.f, 0.f, 0.f, 0.f, 0.f, 0.f};
    add8(zs, a1);
    add8(zs, a2);

    int fi = node * 16 + lane * 2;
    float4 e0f = emb[fi];
    float4 e1f = emb[fi + 1];
    float4 r0, r1;
    r0.x = (e0f.x + zs[0] * sq + acc[0] * rsq) * 0.25f;
    r0.y = (e0f.y + zs[1] * sq + acc[1] * rsq) * 0.25f;
    r0.z = (e0f.z + zs[2] * sq + acc[2] * rsq) * 0.25f;
    r0.w = (e0f.w + zs[3] * sq + acc[3] * rsq) * 0.25f;
    r1.x = (e1f.x + zs[4] * sq + acc[4] * rsq) * 0.25f;
    r1.y = (e1f.y + zs[5] * sq + acc[5] * rsq) * 0.25f;
    r1.z = (e1f.z + zs[6] * sq + acc[6] * rsq) * 0.25f;
    r1.w = (e1f.w + zs[7] * sq + acc[7] * rsq) * 0.25f;
    out[fi]     = r0;
    out[fi + 1] = r1;
}

// ------------- launch --------------------------------------------------------

extern "C" void kernel_launch(void* const* d_in, const int* in_sizes, int n_in,
                              void* d_out, int out_size) {
    const void*  ei  = d_in[0];
    const float* emb = (const float*)d_in[1];
    const int E = in_sizes[0] / 2;

    const int T = 256;
    const int ePairBlocks = ((E + 1) / 2 + T - 1) / T;
    const int gBlocks     = (N_NODES * LPN + T - 1) / T;

    k_pre<<<1, 256>>>((const long long*)ei);
    k_hist<<<ePairBlocks, T>>>(ei, E);
    k_scan_init<<<SCAN_BLOCKS, SCAN_CHUNK>>>((const float4*)emb);
    k_place<<<ePairBlocks, T>>>(ei, E);

    __half *z0, *z1, *z2;
    cudaGetSymbolAddress((void**)&z0, g_z0);
    cudaGetSymbolAddress((void**)&z1, g_z1);
    cudaGetSymbolAddress((void**)&z2, g_z2);

    k_gather<<<gBlocks, T>>>(z0, z1);
    k_gather<<<gBlocks, T>>>(z1, z2);
    k_gather_final<<<gBlocks, T>>>(z2, z1, (const float4*)emb, (float4*)d_out);
}

// round 15
// speedup vs baseline: 1.1231x; 1.1231x over previous
#include <cuda_runtime.h>
#include <cuda_bf16.h>
#include <cuda_fp16.h>
#include <cstdint>

#define N_USERS   100000
#define N_NODES   150000
#define EMB_DIM   64
#define LPN       8             // lanes per node (each lane: 8 halves = 16 B)
#define MAXE      2000000
#define SCAN_CHUNK 1024
#define SCAN_BLOCKS ((N_NODES + SCAN_CHUNK - 1) / SCAN_CHUNK)  // 147

// ------------- static scratch (no allocations allowed) -----------------------
// g_hist is zero-initialized at module load; every launch leaves it re-zeroed.
__device__ int                g_is64;
__device__ int                g_hist[N_NODES];
__device__ int                g_off[N_NODES + 1];   // after k_place: inclusive ends
__device__ unsigned long long g_agg[SCAN_BLOCKS];   // bit63=ready | aggregate
__device__ int                g_src[MAXE];          // CSR: source only
// half-precision z buffers (z = deg^{-1/2} * x): 64 halves (128 B) per node row
__device__ __half g_z0[(size_t)N_NODES * EMB_DIM];
__device__ __half g_z1[(size_t)N_NODES * EMB_DIM];
__device__ __half g_z2[(size_t)N_NODES * EMB_DIM];

// ------------- helpers --------------------------------------------------------
__device__ __forceinline__ void add8(float* acc, uint4 v) {
    float2 f0 = __half22float2(*(__half2*)&v.x);
    float2 f1 = __half22float2(*(__half2*)&v.y);
    float2 f2 = __half22float2(*(__half2*)&v.z);
    float2 f3 = __half22float2(*(__half2*)&v.w);
    acc[0] += f0.x; acc[1] += f0.y;
    acc[2] += f1.x; acc[3] += f1.y;
    acc[4] += f2.x; acc[5] += f2.y;
    acc[6] += f3.x; acc[7] += f3.y;
}

__device__ __forceinline__ int clampn(long long v) {
    if (v < 0) v = 0;
    if (v >= N_NODES) v = N_NODES - 1;
    return (int)v;
}

// batched gather core: 8 lanes cooperatively stream the node's src list.
// One coalesced CSR load per 8 edges; 8 independent predicated row-gathers.
__device__ __forceinline__ void gather_rows(const uint4* __restrict__ x,
                                            int s, int e, int lane, float* acc) {
    for (int base = s; base < e; base += 8) {
        int p = base + lane;
        int src_l = (p < e) ? __ldg(&g_src[p]) : 0;
        int srcs[8];
        #pragma unroll
        for (int j = 0; j < 8; j++)
            srcs[j] = __shfl_sync(0xffffffffu, src_l, j, 8);
        #pragma unroll
        for (int j = 0; j < 8; j++) {
            if (base + j < e) {
                uint4 v = __ldg(&x[srcs[j] * LPN + lane]);
                add8(acc, v);
            }
        }
    }
}

// ------------- tiny pre-pass: zero lookback flags + dtype detect -------------
__global__ void k_pre(const long long* __restrict__ ei) {
    int t = threadIdx.x;
    if (t < SCAN_BLOCKS) g_agg[t] = 0ULL;
    if (t == 0) {
        int ok = 1;
        for (int k = 0; k < 256; k++) {
            long long v = ei[k];
            if (v < 0 || v >= N_NODES) { ok = 0; break; }
        }
        g_is64 = ok;
    }
}

// degree histogram of col — 2 edges per thread, RED (no return value!)
__global__ void k_hist(const void* __restrict__ ei, int E) {
    int t = blockIdx.x * blockDim.x + threadIdx.x;
    int e = t * 2;
    if (e >= E) return;
    int c0, c1 = -1;
    if (g_is64) {
        longlong2 cc = __ldg(&((const longlong2*)ei)[(E + e) >> 1]);
        c0 = clampn(cc.x);
        if (e + 1 < E) c1 = clampn(cc.y);
    } else {
        int2 cc = __ldg(&((const int2*)ei)[(E + e) >> 1]);
        c0 = clampn((long long)cc.x);
        if (e + 1 < E) c1 = clampn((long long)cc.y);
    }
    atomicAdd(&g_hist[c0], 1);
    if (c1 >= 0) atomicAdd(&g_hist[c1], 1);
}

// ------------- fused scan (decoupled lookback, single wave) + z0 init --------
// 147 blocks x 1024 threads: all blocks co-resident on 148 SMs, spin is safe.
// Also re-zeroes g_hist for the next launch (sole consumer of the histogram).
__global__ void __launch_bounds__(SCAN_CHUNK)
k_scan_init(const float4* __restrict__ emb) {
    __shared__ int   s[SCAN_CHUNK];
    __shared__ float sdis[SCAN_CHUNK];
    __shared__ int   sbase;

    int t   = threadIdx.x;
    int b   = blockIdx.x;
    int idx = b * SCAN_CHUNK + t;

    int val = (idx < N_NODES) ? g_hist[idx] : 0;
    if (idx < N_NODES) g_hist[idx] = 0;              // ready for next launch
    sdis[t] = (val > 0) ? rsqrtf((float)val) : 0.0f;
    s[t] = val;
    if (t == 0) sbase = 0;
    __syncthreads();

    // inclusive Hillis-Steele scan of the chunk
    for (int o = 1; o < SCAN_CHUNK; o <<= 1) {
        int v = (t >= o) ? s[t - o] : 0;
        __syncthreads();
        s[t] += v;
        __syncthreads();
    }
    int incl  = s[t];
    int total = s[SCAN_CHUNK - 1];

    // publish this block's aggregate (bit63 = ready flag, single-word protocol)
    if (t == 0)
        atomicExch(&g_agg[b], (1ULL << 63) | (unsigned long long)(unsigned)total);

    // lookback: thread t (< b) waits for predecessor t's aggregate
    if (t < b) {
        unsigned long long w;
        do { w = atomicAdd(&g_agg[t], 0ULL); } while (!(w >> 63));
        atomicAdd(&sbase, (int)(unsigned)w);
    }
    __syncthreads();
    int base = sbase;

    if (idx < N_NODES)      g_off[idx] = base + incl - val;   // exclusive start
    if (idx == N_NODES - 1) g_off[N_NODES] = base + incl;

    // ---- fused z0 init for this block's node chunk (coalesced) ----
    int vbase = b * SCAN_CHUNK * 16;
    #pragma unroll
    for (int k = 0; k < 16; k++) {
        int local = k * SCAN_CHUNK + t;          // 0 .. 16383
        int vi = vbase + local;
        if (vi >= N_NODES * 16) break;
        float dis = sdis[local >> 4];
        float4 v = __ldg(&emb[vi]);
        __half2 h0 = __floats2half2_rn(v.x * dis, v.y * dis);
        __half2 h1 = __floats2half2_rn(v.z * dis, v.w * dis);
        uint2 packed;
        packed.x = *(unsigned int*)&h0;
        packed.y = *(unsigned int*)&h1;
        ((uint2*)g_z0)[vi] = packed;
    }
}

// --- place edges: g_off doubles as the allocator (atomic return = position) --
// After this kernel, g_off[c] = inclusive end of c's list (start = g_off[c-1]).
__global__ void k_place(const void* __restrict__ ei, int E) {
    int t = blockIdx.x * blockDim.x + threadIdx.x;
    int e = t * 2;
    if (e >= E) return;
    int r0, c0, r1 = -1, c1 = -1;
    if (g_is64) {
        longlong2 rr = __ldg(&((const longlong2*)ei)[e >> 1]);
        longlong2 cc = __ldg(&((const longlong2*)ei)[(E + e) >> 1]);
        r0 = clampn(rr.x); c0 = clampn(cc.x);
        if (e + 1 < E) { r1 = clampn(rr.y); c1 = clampn(cc.y); }
    } else {
        int2 rr = __ldg(&((const int2*)ei)[e >> 1]);
        int2 cc = __ldg(&((const int2*)ei)[(E + e) >> 1]);
        r0 = clampn((long long)rr.x); c0 = clampn((long long)cc.x);
        if (e + 1 < E) { r1 = clampn((long long)rr.y); c1 = clampn((long long)cc.y); }
    }
    int p0 = atomicAdd(&g_off[c0], 1);
    g_src[p0] = r0;
    if (r1 >= 0) {
        int p1 = atomicAdd(&g_off[c1], 1);
        g_src[p1] = r1;
    }
}

// ------------- gather layer: z_out[c] = (sum z_in[src]) / deg[c] -------------
// shifted CSR convention: start = g_off[node-1] (0 for node 0), end = g_off[node]
__global__ void __launch_bounds__(256)
k_gather(const __half* __restrict__ zin, __half* __restrict__ zout) {
    int gid  = blockIdx.x * blockDim.x + threadIdx.x;
    int node = gid >> 3;
    int lane = gid & 7;
    if (node >= N_NODES) return;

    const uint4* __restrict__ x = (const uint4*)zin;
    int s = (node > 0) ? __ldg(&g_off[node - 1]) : 0;
    int e = __ldg(&g_off[node]);

    float acc[8] = {0.f, 0.f, 0.f, 0.f, 0.f, 0.f, 0.f, 0.f};
    gather_rows(x, s, e, lane, acc);

    int deg = e - s;
    float inv = (deg > 0) ? (1.0f / (float)deg) : 0.0f;
    __half2 o0 = __floats2half2_rn(acc[0] * inv, acc[1] * inv);
    __half2 o1 = __floats2half2_rn(acc[2] * inv, acc[3] * inv);
    __half2 o2 = __floats2half2_rn(acc[4] * inv, acc[5] * inv);
    __half2 o3 = __floats2half2_rn(acc[6] * inv, acc[7] * inv);
    uint4 packed;
    packed.x = *(unsigned int*)&o0;
    packed.y = *(unsigned int*)&o1;
    packed.z = *(unsigned int*)&o2;
    packed.w = *(unsigned int*)&o3;
    ((uint4*)zout)[node * LPN + lane] = packed;
}

// ------------- final gather fused with combine -------------------------------
// S3 = sum z2[src]; out = (emb + (z1+z2)*sqrt(deg) + S3*rsqrt(deg)) / 4
__global__ void __launch_bounds__(256)
k_gather_final(const __half* __restrict__ z2h,
               const __half* __restrict__ z1h,
               const float4* __restrict__ emb,
               float4* __restrict__ out) {
    int gid  = blockIdx.x * blockDim.x + threadIdx.x;
    int node = gid >> 3;
    int lane = gid & 7;
    if (node >= N_NODES) return;

    const uint4* __restrict__ x = (const uint4*)z2h;
    int s = (node > 0) ? __ldg(&g_off[node - 1]) : 0;
    int e = __ldg(&g_off[node]);

    float acc[8] = {0.f, 0.f, 0.f, 0.f, 0.f, 0.f, 0.f, 0.f};
    gather_rows(x, s, e, lane, acc);

    int deg = e - s;
    float fdeg = (float)deg;
    float rsq  = (deg > 0) ? rsqrtf(fdeg) : 0.0f;   // x3 scale
    float sq   = (deg > 0) ? sqrtf(fdeg)  : 0.0f;   // x1,x2 scale

    uint4 a1 = ((const uint4*)z1h)[node * LPN + lane];
    uint4 a2 = x[node * LPN + lane];
    float zs[8] = {0.f, 0.f, 0.f, 0.f, 0.f, 0.f, 0.f, 0.f};
    add8(zs, a1);
    add8(zs, a2);

    int fi = node * 16 + lane * 2;
    float4 e0f = emb[fi];
    float4 e1f = emb[fi + 1];
    float4 r0, r1;
    r0.x = (e0f.x + zs[0] * sq + acc[0] * rsq) * 0.25f;
    r0.y = (e0f.y + zs[1] * sq + acc[1] * rsq) * 0.25f;
    r0.z = (e0f.z + zs[2] * sq + acc[2] * rsq) * 0.25f;
    r0.w = (e0f.w + zs[3] * sq + acc[3] * rsq) * 0.25f;
    r1.x = (e1f.x + zs[4] * sq + acc[4] * rsq) * 0.25f;
    r1.y = (e1f.y + zs[5] * sq + acc[5] * rsq) * 0.25f;
    r1.z = (e1f.z + zs[6] * sq + acc[6] * rsq) * 0.25f;
    r1.w = (e1f.w + zs[7] * sq + acc[7] * rsq) * 0.25f;
    out[fi]     = r0;
    out[fi + 1] = r1;
}

// ------------- launch --------------------------------------------------------

extern "C" void kernel_launch(void* const* d_in, const int* in_sizes, int n_in,
                              void* d_out, int out_size) {
    const void*  ei  = d_in[0];
    const float* emb = (const float*)d_in[1];
    const int E = in_sizes[0] / 2;

    const int T = 256;
    const int ePairBlocks = ((E + 1) / 2 + T - 1) / T;
    const int gBlocks     = (N_NODES * LPN + T - 1) / T;

    k_pre<<<1, 256>>>((const long long*)ei);
    k_hist<<<ePairBlocks, T>>>(ei, E);
    k_scan_init<<<SCAN_BLOCKS, SCAN_CHUNK>>>((const float4*)emb);
    k_place<<<ePairBlocks, T>>>(ei, E);

    __half *z0, *z1, *z2;
    cudaGetSymbolAddress((void**)&z0, g_z0);
    cudaGetSymbolAddress((void**)&z1, g_z1);
    cudaGetSymbolAddress((void**)&z2, g_z2);

    k_gather<<<gBlocks, T>>>(z0, z1);
    k_gather<<<gBlocks, T>>>(z1, z2);
    k_gather_final<<<gBlocks, T>>>(z2, z1, (const float4*)emb, (float4*)d_out);
}

// round 16
// speedup vs baseline: 1.4213x; 1.2656x over previous
#include <cuda_runtime.h>
#include <cuda_bf16.h>
#include <cuda_fp16.h>
#include <cstdint>

#define N_USERS   100000
#define N_NODES   150000
#define EMB_DIM   64
#define LPN       8             // lanes per node (each lane: 8 halves = 16 B)
#define MAXE      2000000
#define SCAN_CHUNK 1024
#define SCAN_BLOCKS ((N_NODES + SCAN_CHUNK - 1) / SCAN_CHUNK)  // 147

// ------------- static scratch (no allocations allowed) -----------------------
// g_hist is zero-initialized at module load; every launch leaves it re-zeroed.
__device__ int                g_is64;
__device__ int                g_hist[N_NODES];
__device__ int                g_off[N_NODES + 1];   // after k_place: inclusive ends
__device__ unsigned long long g_agg[SCAN_BLOCKS];   // bit63=ready | aggregate
__device__ int                g_src[MAXE];          // CSR: source only
// half-precision z buffers (z = deg^{-1/2} * x): 64 halves (128 B) per node row
__device__ __half g_z0[(size_t)N_NODES * EMB_DIM];
__device__ __half g_z1[(size_t)N_NODES * EMB_DIM];
__device__ __half g_z2[(size_t)N_NODES * EMB_DIM];

// ------------- helpers --------------------------------------------------------
__device__ __forceinline__ void add8(float* acc, uint4 v) {
    float2 f0 = __half22float2(*(__half2*)&v.x);
    float2 f1 = __half22float2(*(__half2*)&v.y);
    float2 f2 = __half22float2(*(__half2*)&v.z);
    float2 f3 = __half22float2(*(__half2*)&v.w);
    acc[0] += f0.x; acc[1] += f0.y;
    acc[2] += f1.x; acc[3] += f1.y;
    acc[4] += f2.x; acc[5] += f2.y;
    acc[6] += f3.x; acc[7] += f3.y;
}

__device__ __forceinline__ int clampn(long long v) {
    if (v < 0) v = 0;
    if (v >= N_NODES) v = N_NODES - 1;
    return (int)v;
}

// plain gather core: 4x unroll (broadcast CSR loads are free in L1),
// then a 2-wide step, then at most one scalar tail iteration.
__device__ __forceinline__ void gather_rows(const uint4* __restrict__ x,
                                            int s, int e, int lane, float* acc) {
    int p = s;
    for (; p + 4 <= e; p += 4) {
        int s0 = __ldg(&g_src[p]);
        int s1 = __ldg(&g_src[p + 1]);
        int s2 = __ldg(&g_src[p + 2]);
        int s3 = __ldg(&g_src[p + 3]);
        uint4 v0 = __ldg(&x[s0 * LPN + lane]);
        uint4 v1 = __ldg(&x[s1 * LPN + lane]);
        uint4 v2 = __ldg(&x[s2 * LPN + lane]);
        uint4 v3 = __ldg(&x[s3 * LPN + lane]);
        add8(acc, v0);
        add8(acc, v1);
        add8(acc, v2);
        add8(acc, v3);
    }
    if (p + 2 <= e) {
        int s0 = __ldg(&g_src[p]);
        int s1 = __ldg(&g_src[p + 1]);
        uint4 v0 = __ldg(&x[s0 * LPN + lane]);
        uint4 v1 = __ldg(&x[s1 * LPN + lane]);
        add8(acc, v0);
        add8(acc, v1);
        p += 2;
    }
    if (p < e) {
        uint4 v0 = __ldg(&x[__ldg(&g_src[p]) * LPN + lane]);
        add8(acc, v0);
    }
}

// ------------- tiny pre-pass: zero lookback flags + dtype detect -------------
__global__ void k_pre(const long long* __restrict__ ei) {
    int t = threadIdx.x;
    if (t < SCAN_BLOCKS) g_agg[t] = 0ULL;
    if (t == 0) {
        int ok = 1;
        for (int k = 0; k < 256; k++) {
            long long v = ei[k];
            if (v < 0 || v >= N_NODES) { ok = 0; break; }
        }
        g_is64 = ok;
    }
}

// degree histogram of col — 2 edges per thread, RED (never use the return!)
__global__ void k_hist(const void* __restrict__ ei, int E) {
    int t = blockIdx.x * blockDim.x + threadIdx.x;
    int e = t * 2;
    if (e >= E) return;
    int c0, c1 = -1;
    if (g_is64) {
        longlong2 cc = __ldg(&((const longlong2*)ei)[(E + e) >> 1]);
        c0 = clampn(cc.x);
        if (e + 1 < E) c1 = clampn(cc.y);
    } else {
        int2 cc = __ldg(&((const int2*)ei)[(E + e) >> 1]);
        c0 = clampn((long long)cc.x);
        if (e + 1 < E) c1 = clampn((long long)cc.y);
    }
    atomicAdd(&g_hist[c0], 1);
    if (c1 >= 0) atomicAdd(&g_hist[c1], 1);
}

// ------------- fused scan (decoupled lookback, single wave) + z0 init --------
// 147 blocks x 1024 threads: all blocks co-resident on 148 SMs, spin is safe.
// Also re-zeroes g_hist for the next launch (sole consumer of the histogram).
__global__ void __launch_bounds__(SCAN_CHUNK)
k_scan_init(const float4* __restrict__ emb) {
    __shared__ int   s[SCAN_CHUNK];
    __shared__ float sdis[SCAN_CHUNK];
    __shared__ int   sbase;

    int t   = threadIdx.x;
    int b   = blockIdx.x;
    int idx = b * SCAN_CHUNK + t;

    int val = (idx < N_NODES) ? g_hist[idx] : 0;
    if (idx < N_NODES) g_hist[idx] = 0;              // ready for next launch
    sdis[t] = (val > 0) ? rsqrtf((float)val) : 0.0f;
    s[t] = val;
    if (t == 0) sbase = 0;
    __syncthreads();

    // inclusive Hillis-Steele scan of the chunk
    for (int o = 1; o < SCAN_CHUNK; o <<= 1) {
        int v = (t >= o) ? s[t - o] : 0;
        __syncthreads();
        s[t] += v;
        __syncthreads();
    }
    int incl  = s[t];
    int total = s[SCAN_CHUNK - 1];

    // publish this block's aggregate (bit63 = ready flag, single-word protocol)
    if (t == 0)
        atomicExch(&g_agg[b], (1ULL << 63) | (unsigned long long)(unsigned)total);

    // lookback: thread t (< b) waits for predecessor t's aggregate
    if (t < b) {
        unsigned long long w;
        do { w = atomicAdd(&g_agg[t], 0ULL); } while (!(w >> 63));
        atomicAdd(&sbase, (int)(unsigned)w);
    }
    __syncthreads();
    int base = sbase;

    if (idx < N_NODES)      g_off[idx] = base + incl - val;   // exclusive start
    if (idx == N_NODES - 1) g_off[N_NODES] = base + incl;

    // ---- fused z0 init for this block's node chunk (coalesced) ----
    int vbase = b * SCAN_CHUNK * 16;
    #pragma unroll
    for (int k = 0; k < 16; k++) {
        int local = k * SCAN_CHUNK + t;          // 0 .. 16383
        int vi = vbase + local;
        if (vi >= N_NODES * 16) break;
        float dis = sdis[local >> 4];
        float4 v = __ldg(&emb[vi]);
        __half2 h0 = __floats2half2_rn(v.x * dis, v.y * dis);
        __half2 h1 = __floats2half2_rn(v.z * dis, v.w * dis);
        uint2 packed;
        packed.x = *(unsigned int*)&h0;
        packed.y = *(unsigned int*)&h1;
        ((uint2*)g_z0)[vi] = packed;
    }
}

// --- place edges: g_off doubles as the allocator (atomic return = position) --
// After this kernel, g_off[c] = inclusive end of c's list (start = g_off[c-1]).
__global__ void k_place(const void* __restrict__ ei, int E) {
    int t = blockIdx.x * blockDim.x + threadIdx.x;
    int e = t * 2;
    if (e >= E) return;
    int r0, c0, r1 = -1, c1 = -1;
    if (g_is64) {
        longlong2 rr = __ldg(&((const longlong2*)ei)[e >> 1]);
        longlong2 cc = __ldg(&((const longlong2*)ei)[(E + e) >> 1]);
        r0 = clampn(rr.x); c0 = clampn(cc.x);
        if (e + 1 < E) { r1 = clampn(rr.y); c1 = clampn(cc.y); }
    } else {
        int2 rr = __ldg(&((const int2*)ei)[e >> 1]);
        int2 cc = __ldg(&((const int2*)ei)[(E + e) >> 1]);
        r0 = clampn((long long)rr.x); c0 = clampn((long long)cc.x);
        if (e + 1 < E) { r1 = clampn((long long)rr.y); c1 = clampn((long long)cc.y); }
    }
    int p0 = atomicAdd(&g_off[c0], 1);
    g_src[p0] = r0;
    if (r1 >= 0) {
        int p1 = atomicAdd(&g_off[c1], 1);
        g_src[p1] = r1;
    }
}

// ------------- gather layer: z_out[c] = (sum z_in[src]) / deg[c] -------------
// shifted CSR convention: start = g_off[node-1] (0 for node 0), end = g_off[node]
__global__ void __launch_bounds__(256)
k_gather(const __half* __restrict__ zin, __half* __restrict__ zout) {
    int gid  = blockIdx.x * blockDim.x + threadIdx.x;
    int node = gid >> 3;
    int lane = gid & 7;
    if (node >= N_NODES) return;

    const uint4* __restrict__ x = (const uint4*)zin;
    int s = (node > 0) ? __ldg(&g_off[node - 1]) : 0;
    int e = __ldg(&g_off[node]);

    float acc[8] = {0.f, 0.f, 0.f, 0.f, 0.f, 0.f, 0.f, 0.f};
    gather_rows(x, s, e, lane, acc);

    int deg = e - s;
    float inv = (deg > 0) ? (1.0f / (float)deg) : 0.0f;
    __half2 o0 = __floats2half2_rn(acc[0] * inv, acc[1] * inv);
    __half2 o1 = __floats2half2_rn(acc[2] * inv, acc[3] * inv);
    __half2 o2 = __floats2half2_rn(acc[4] * inv, acc[5] * inv);
    __half2 o3 = __floats2half2_rn(acc[6] * inv, acc[7] * inv);
    uint4 packed;
    packed.x = *(unsigned int*)&o0;
    packed.y = *(unsigned int*)&o1;
    packed.z = *(unsigned int*)&o2;
    packed.w = *(unsigned int*)&o3;
    ((uint4*)zout)[node * LPN + lane] = packed;
}

// ------------- final gather fused with combine -------------------------------
// S3 = sum z2[src]; out = (emb + (z1+z2)*sqrt(deg) + S3*rsqrt(deg)) / 4
__global__ void __launch_bounds__(256)
k_gather_final(const __half* __restrict__ z2h,
               const __half* __restrict__ z1h,
               const float4* __restrict__ emb,
               float4* __restrict__ out) {
    int gid  = blockIdx.x * blockDim.x + threadIdx.x;
    int node = gid >> 3;
    int lane = gid & 7;
    if (node >= N_NODES) return;

    const uint4* __restrict__ x = (const uint4*)z2h;
    int s = (node > 0) ? __ldg(&g_off[node - 1]) : 0;
    int e = __ldg(&g_off[node]);

    float acc[8] = {0.f, 0.f, 0.f, 0.f, 0.f, 0.f, 0.f, 0.f};
    gather_rows(x, s, e, lane, acc);

    int deg = e - s;
    float fdeg = (float)deg;
    float rsq  = (deg > 0) ? rsqrtf(fdeg) : 0.0f;   // x3 scale
    float sq   = (deg > 0) ? sqrtf(fdeg)  : 0.0f;   // x1,x2 scale

    uint4 a1 = ((const uint4*)z1h)[node * LPN + lane];
    uint4 a2 = x[node * LPN + lane];
    float zs[8] = {0.f, 0.f, 0.f, 0.f, 0.f, 0.f, 0.f, 0.f};
    add8(zs, a1);
    add8(zs, a2);

    int fi = node * 16 + lane * 2;
    float4 e0f = emb[fi];
    float4 e1f = emb[fi + 1];
    float4 r0, r1;
    r0.x = (e0f.x + zs[0] * sq + acc[0] * rsq) * 0.25f;
    r0.y = (e0f.y + zs[1] * sq + acc[1] * rsq) * 0.25f;
    r0.z = (e0f.z + zs[2] * sq + acc[2] * rsq) * 0.25f;
    r0.w = (e0f.w + zs[3] * sq + acc[3] * rsq) * 0.25f;
    r1.x = (e1f.x + zs[4] * sq + acc[4] * rsq) * 0.25f;
    r1.y = (e1f.y + zs[5] * sq + acc[5] * rsq) * 0.25f;
    r1.z = (e1f.z + zs[6] * sq + acc[6] * rsq) * 0.25f;
    r1.w = (e1f.w + zs[7] * sq + acc[7] * rsq) * 0.25f;
    out[fi]     = r0;
    out[fi + 1] = r1;
}

// ------------- launch --------------------------------------------------------

extern "C" void kernel_launch(void* const* d_in, const int* in_sizes, int n_in,
                              void* d_out, int out_size) {
    const void*  ei  = d_in[0];
    const float* emb = (const float*)d_in[1];
    const int E = in_sizes[0] / 2;

    const int T = 256;
    const int ePairBlocks = ((E + 1) / 2 + T - 1) / T;
    const int gBlocks     = (N_NODES * LPN + T - 1) / T;

    k_pre<<<1, 256>>>((const long long*)ei);
    k_hist<<<ePairBlocks, T>>>(ei, E);
    k_scan_init<<<SCAN_BLOCKS, SCAN_CHUNK>>>((const float4*)emb);
    k_place<<<ePairBlocks, T>>>(ei, E);

    __half *z0, *z1, *z2;
    cudaGetSymbolAddress((void**)&z0, g_z0);
    cudaGetSymbolAddress((void**)&z1, g_z1);
    cudaGetSymbolAddress((void**)&z2, g_z2);

    k_gather<<<gBlocks, T>>>(z0, z1);
    k_gather<<<gBlocks, T>>>(z1, z2);
    k_gather_final<<<gBlocks, T>>>(z2, z1, (const float4*)emb, (float4*)d_out);
}